// round 5
// baseline (speedup 1.0000x reference)
#include <cuda_runtime.h>
#include <cuda_bf16.h>

// Seq2SeqLoss: label-smoothed weighted cross-entropy, mean over masked rows.
// Harness canonical dtypes:
//   [0] outputs  f32 [B*S*C] = 131072000
//   [1] gold     i32 [B*S]   = 4096
//   [2] mask     i32 [B*S]   = 4096
//   [3] weight   f32 [C]     = 32000
// output: f32 scalar

#define SMOOTHING 0.1f
#define EPSILON   1e-8f

__device__ float g_loss_acc;   // zero-initialized; finalize resets after read
__device__ float g_mask_acc;

// All-FMA exp (no MUFU): exp(x) = 2^(x*log2e), magic-number round,
// degree-5 poly for 2^f on [-0.5,0.5] (rel err ~2.4e-6), exponent splice.
__device__ __forceinline__ float fexp(float x) {
    float t = x * 1.4426950408889634f;
    t = fminf(fmaxf(t, -126.0f), 126.0f);
    float r = t + 12582912.0f;
    int   eb = __float_as_int(r) << 23;
    float nf = r - 12582912.0f;
    float f  = t - nf;
    float p  = 1.3333558146428443e-3f;
    p = fmaf(p, f, 9.6181291076284772e-3f);
    p = fmaf(p, f, 5.5504108664821580e-2f);
    p = fmaf(p, f, 2.4022650695910072e-1f);
    p = fmaf(p, f, 6.9314718055994531e-1f);
    p = fmaf(p, f, 1.0f);
    return __int_as_float(__float_as_int(p) + eb);
}

__device__ __forceinline__ float warp_sum(float v) {
    #pragma unroll
    for (int o = 16; o > 0; o >>= 1) v += __shfl_xor_sync(0xffffffffu, v, o);
    return v;
}

// One CTA per row. Stream logits once (__ldcs, evict-first); weight via __ldg.
// Accumulate sum_exp, dot(x,w), sumW in one pass; CTA epilogue computes the
// complete per-row loss and atomically accumulates into global scalars.
__global__ __launch_bounds__(256) void row_loss_kernel(
    const float* __restrict__ logits,
    const int*   __restrict__ gold,
    const int*   __restrict__ mask,
    const float* __restrict__ weight,
    int C4, int C)
{
    const int row = blockIdx.x;
    if (mask[row] == 0) return;            // masked rows contribute nothing

    const float4* lp = reinterpret_cast<const float4*>(logits) + (size_t)row * C4;
    const float4* wp = reinterpret_cast<const float4*>(weight);

    // Gold gather issued early (latency hidden under the stream), thread 0 only.
    float xg = 0.0f, wg = 0.0f;
    int g = gold[row];
    if (threadIdx.x == 0) {
        xg = __ldg(logits + (size_t)row * C + (size_t)g);
        wg = __ldg(weight + g);
    }

    float s = 0.0f, d = 0.0f, wsum = 0.0f;
    #pragma unroll 4
    for (int i = threadIdx.x; i < C4; i += 256) {
        float4 x = __ldcs(lp + i);
        float4 w = __ldg(wp + i);
        d = fmaf(x.x, w.x, d);
        d = fmaf(x.y, w.y, d);
        d = fmaf(x.z, w.z, d);
        d = fmaf(x.w, w.w, d);
        wsum += w.x + w.y + w.z + w.w;
        s += fexp(x.x);
        s += fexp(x.y);
        s += fexp(x.z);
        s += fexp(x.w);
    }

    __shared__ float sh_s[8], sh_d[8], sh_w[8];
    s    = warp_sum(s);
    d    = warp_sum(d);
    wsum = warp_sum(wsum);
    const int wid = threadIdx.x >> 5;
    const int lid = threadIdx.x & 31;
    if (lid == 0) { sh_s[wid] = s; sh_d[wid] = d; sh_w[wid] = wsum; }
    __syncthreads();

    if (threadIdx.x == 0) {
        float ss = 0.0f, dd = 0.0f, ww = 0.0f;
        #pragma unroll
        for (int k = 0; k < 8; k++) { ss += sh_s[k]; dd += sh_d[k]; ww += sh_w[k]; }

        const float uniform = SMOOTHING / (float)(C - 1);
        const float conf    = 1.0f - SMOOTHING;
        const float cmu     = conf - uniform;

        float lse  = logf(ss);
        float loss = uniform * fmaf(ww, lse, -dd) + cmu * wg * (lse - xg);
        atomicAdd(&g_loss_acc, loss);
        atomicAdd(&g_mask_acc, 1.0f);
    }
}

// Tail: divide and reset accumulators (keeps graph replays deterministic).
__global__ void finalize2_kernel(float* __restrict__ out) {
    out[0] = g_loss_acc / (g_mask_acc + EPSILON);
    g_loss_acc = 0.0f;
    g_mask_acc = 0.0f;
}

extern "C" void kernel_launch(void* const* d_in, const int* in_sizes, int n_in,
                              void* d_out, int out_size)
{
    const float* logits = (const float*)d_in[0];
    const int*   gold   = (const int*)d_in[1];
    const int*   mask   = (const int*)d_in[2];
    const float* weight = (const float*)d_in[3];
    float*       out    = (float*)d_out;

    const int N = in_sizes[1];     // B*S rows
    const int C = in_sizes[3];     // classes
    const int C4 = C / 4;

    row_loss_kernel<<<N, 256>>>(logits, gold, mask, weight, C4, C);
    finalize2_kernel<<<1, 1>>>(out);
}

// round 6
// speedup vs baseline: 1.0941x; 1.0941x over previous
#include <cuda_runtime.h>
#include <cuda_bf16.h>

// Seq2SeqLoss: label-smoothed weighted cross-entropy, mean over masked rows.
// Harness canonical dtypes:
//   [0] outputs  f32 [B*S*C] = 131072000
//   [1] gold     i32 [B*S]   = 4096
//   [2] mask     i32 [B*S]   = 4096
//   [3] weight   f32 [C]     = 32000
// output: f32 scalar

#define SMOOTHING 0.1f
#define EPSILON   1e-8f

__device__ float g_sumw;       // written fresh by sumw_kernel each replay
__device__ float g_loss_acc;   // zero-init; finalize resets after read
__device__ float g_mask_acc;

// All-FMA exp (no MUFU): exp(x) = 2^(x*log2e), magic-number round,
// degree-5 poly for 2^f on [-0.5,0.5] (rel err ~2.4e-6), exponent splice.
__device__ __forceinline__ float fexp(float x) {
    float t = x * 1.4426950408889634f;
    t = fminf(fmaxf(t, -126.0f), 126.0f);
    float r = t + 12582912.0f;
    int   eb = __float_as_int(r) << 23;
    float nf = r - 12582912.0f;
    float f  = t - nf;
    float p  = 1.3333558146428443e-3f;
    p = fmaf(p, f, 9.6181291076284772e-3f);
    p = fmaf(p, f, 5.5504108664821580e-2f);
    p = fmaf(p, f, 2.4022650695910072e-1f);
    p = fmaf(p, f, 6.9314718055994531e-1f);
    p = fmaf(p, f, 1.0f);
    return __int_as_float(__float_as_int(p) + eb);
}

__device__ __forceinline__ float warp_sum(float v) {
    #pragma unroll
    for (int o = 16; o > 0; o >>= 1) v += __shfl_xor_sync(0xffffffffu, v, o);
    return v;
}

// Pre-kernel: sumW = sum(weight), one CTA, plain store (deterministic).
__global__ __launch_bounds__(1024) void sumw_kernel(
    const float* __restrict__ weight, int C4)
{
    const float4* wp = reinterpret_cast<const float4*>(weight);
    float w = 0.0f;
    for (int i = threadIdx.x; i < C4; i += 1024) {
        float4 v = __ldg(wp + i);
        w += v.x + v.y + v.z + v.w;
    }
    __shared__ float sh[32];
    w = warp_sum(w);
    if ((threadIdx.x & 31) == 0) sh[threadIdx.x >> 5] = w;
    __syncthreads();
    if (threadIdx.x < 32) {
        float v = sh[threadIdx.x];
        v = warp_sum(v);
        if (threadIdx.x == 0) g_sumw = v;
    }
}

// One CTA per row. Streaming loop is IDENTICAL to the proven 82us version:
// only s (sum exp) and d (dot x,w) accumulate per element. Gold gather issued
// pre-loop; epilogue computes the full per-row loss with precomputed sumW.
__global__ __launch_bounds__(256) void row_loss_kernel(
    const float* __restrict__ logits,
    const int*   __restrict__ gold,
    const int*   __restrict__ mask,
    const float* __restrict__ weight,
    int C4, int C)
{
    const int row = blockIdx.x;

    const float4* lp = reinterpret_cast<const float4*>(logits) + (size_t)row * C4;
    const float4* wp = reinterpret_cast<const float4*>(weight);

    // Early gold gather (thread 0): latency drains under the stream.
    float xg = 0.0f, wg = 0.0f;
    int   m  = 1;
    if (threadIdx.x == 0) {
        m = mask[row];
        int g = gold[row];
        xg = __ldg(logits + (size_t)row * C + (size_t)g);
        wg = __ldg(weight + g);
    }

    float s = 0.0f, d = 0.0f;
    #pragma unroll 4
    for (int i = threadIdx.x; i < C4; i += 256) {
        float4 x = __ldcs(lp + i);
        float4 w = __ldg(wp + i);
        d = fmaf(x.x, w.x, d);
        d = fmaf(x.y, w.y, d);
        d = fmaf(x.z, w.z, d);
        d = fmaf(x.w, w.w, d);
        s += fexp(x.x);
        s += fexp(x.y);
        s += fexp(x.z);
        s += fexp(x.w);
    }

    __shared__ float sh_s[8], sh_d[8];
    s = warp_sum(s);
    d = warp_sum(d);
    const int wid = threadIdx.x >> 5;
    const int lid = threadIdx.x & 31;
    if (lid == 0) { sh_s[wid] = s; sh_d[wid] = d; }
    __syncthreads();

    if (threadIdx.x == 0 && m != 0) {
        float ss = 0.0f, dd = 0.0f;
        #pragma unroll
        for (int k = 0; k < 8; k++) { ss += sh_s[k]; dd += sh_d[k]; }

        const float uniform = SMOOTHING / (float)(C - 1);
        const float conf    = 1.0f - SMOOTHING;
        const float cmu     = conf - uniform;

        float lse  = logf(ss);
        float loss = uniform * fmaf(g_sumw, lse, -dd) + cmu * wg * (lse - xg);
        atomicAdd(&g_loss_acc, loss);
        atomicAdd(&g_mask_acc, 1.0f);
    }
}

// Tail: divide and reset accumulators (graph replays stay deterministic).
__global__ void finalize2_kernel(float* __restrict__ out) {
    out[0] = g_loss_acc / (g_mask_acc + EPSILON);
    g_loss_acc = 0.0f;
    g_mask_acc = 0.0f;
}

extern "C" void kernel_launch(void* const* d_in, const int* in_sizes, int n_in,
                              void* d_out, int out_size)
{
    const float* logits = (const float*)d_in[0];
    const int*   gold   = (const int*)d_in[1];
    const int*   mask   = (const int*)d_in[2];
    const float* weight = (const float*)d_in[3];
    float*       out    = (float*)d_out;

    const int N = in_sizes[1];     // B*S rows
    const int C = in_sizes[3];     // classes
    const int C4 = C / 4;

    sumw_kernel<<<1, 1024>>>(weight, C4);
    row_loss_kernel<<<N, 256>>>(logits, gold, mask, weight, C4, C);
    finalize2_kernel<<<1, 1>>>(out);
}

// round 7
// speedup vs baseline: 1.1958x; 1.0929x over previous
#include <cuda_runtime.h>
#include <cuda_bf16.h>

// Seq2SeqLoss: label-smoothed weighted cross-entropy, mean over masked rows.
// Harness canonical dtypes:
//   [0] outputs  f32 [B*S*C] = 131072000
//   [1] gold     i32 [B*S]   = 4096
//   [2] mask     i32 [B*S]   = 4096
//   [3] weight   f32 [C]     = 32000
// output: f32 scalar
//
// Sum factorization: with lse_r = log(sum_c exp(x_rc)), dd_r = sum_c w_c x_rc,
//   sum_r loss_r = uniform*(sumW*Σlse − Σdd) + (conf−uniform)*Σ w_g (lse − x_g)
// so sumW is only needed once, at the very end.

#define SMOOTHING 0.1f
#define EPSILON   1e-8f
#define SUMW_CTAS 8

__device__ float g_sumw;       // atomic-accumulated by SUMW_CTAS extra CTAs
__device__ float g_lse_acc;    // all reset by finalize each replay
__device__ float g_dot_acc;
__device__ float g_gold_acc;
__device__ float g_mask_acc;

// All-FMA exp (no MUFU): exp(x) = 2^(x*log2e), magic-number round,
// degree-5 poly for 2^f on [-0.5,0.5] (rel err ~2.4e-6), exponent splice.
__device__ __forceinline__ float fexp(float x) {
    float t = x * 1.4426950408889634f;
    t = fminf(fmaxf(t, -126.0f), 126.0f);
    float r = t + 12582912.0f;
    int   eb = __float_as_int(r) << 23;
    float nf = r - 12582912.0f;
    float f  = t - nf;
    float p  = 1.3333558146428443e-3f;
    p = fmaf(p, f, 9.6181291076284772e-3f);
    p = fmaf(p, f, 5.5504108664821580e-2f);
    p = fmaf(p, f, 2.4022650695910072e-1f);
    p = fmaf(p, f, 6.9314718055994531e-1f);
    p = fmaf(p, f, 1.0f);
    return __int_as_float(__float_as_int(p) + eb);
}

__device__ __forceinline__ float warp_sum(float v) {
    #pragma unroll
    for (int o = 16; o > 0; o >>= 1) v += __shfl_xor_sync(0xffffffffu, v, o);
    return v;
}

// Grid = N + SUMW_CTAS.
// CTAs [0, N):      one row each — stream logits (proven R4 loop), then
//                   post-loop gold gather + 4 scalar REDs.
// CTAs [N, N+8):    sum a slice of weight into g_sumw (runs in the shadow
//                   of the streaming CTAs).
__global__ __launch_bounds__(256) void row_loss_kernel(
    const float* __restrict__ logits,
    const int*   __restrict__ gold,
    const int*   __restrict__ mask,
    const float* __restrict__ weight,
    int C4, int C, int N)
{
    const int bid = blockIdx.x;
    const float4* wp = reinterpret_cast<const float4*>(weight);

    if (bid >= N) {
        // ---- sumW slice CTA ----
        const int slice = bid - N;
        const int per   = (C4 + SUMW_CTAS - 1) / SUMW_CTAS;
        const int lo    = slice * per;
        const int hi    = min(lo + per, C4);
        float w = 0.0f;
        for (int i = lo + threadIdx.x; i < hi; i += 256) {
            float4 v = __ldg(wp + i);
            w += v.x + v.y + v.z + v.w;
        }
        __shared__ float shw[8];
        w = warp_sum(w);
        if ((threadIdx.x & 31) == 0) shw[threadIdx.x >> 5] = w;
        __syncthreads();
        if (threadIdx.x == 0) {
            float ww = 0.0f;
            #pragma unroll
            for (int k = 0; k < 8; k++) ww += shw[k];
            atomicAdd(&g_sumw, ww);
        }
        return;
    }

    // ---- row CTA: streaming loop identical to the proven 82us version ----
    const int row = bid;
    const float4* lp = reinterpret_cast<const float4*>(logits) + (size_t)row * C4;

    float s = 0.0f, d = 0.0f;
    #pragma unroll 4
    for (int i = threadIdx.x; i < C4; i += 256) {
        float4 x = __ldcs(lp + i);
        float4 w = __ldg(wp + i);
        d = fmaf(x.x, w.x, d);
        d = fmaf(x.y, w.y, d);
        d = fmaf(x.z, w.z, d);
        d = fmaf(x.w, w.w, d);
        s += fexp(x.x);
        s += fexp(x.y);
        s += fexp(x.z);
        s += fexp(x.w);
    }

    __shared__ float sh_s[8], sh_d[8];
    s = warp_sum(s);
    d = warp_sum(d);
    const int wid = threadIdx.x >> 5;
    const int lid = threadIdx.x & 31;
    if (lid == 0) { sh_s[wid] = s; sh_d[wid] = d; }
    __syncthreads();

    if (threadIdx.x == 0) {
        int m = mask[row];
        if (m != 0) {
            float ss = 0.0f, dd = 0.0f;
            #pragma unroll
            for (int k = 0; k < 8; k++) { ss += sh_s[k]; dd += sh_d[k]; }

            int   g   = gold[row];
            float xg  = __ldg(logits + (size_t)row * C + (size_t)g);
            float wg  = __ldg(weight + g);
            float lse = logf(ss);

            atomicAdd(&g_lse_acc,  lse);
            atomicAdd(&g_dot_acc,  dd);
            atomicAdd(&g_gold_acc, wg * (lse - xg));
            atomicAdd(&g_mask_acc, 1.0f);
        }
    }
}

// Tail: combine with sumW, divide, reset all accumulators.
__global__ void finalize3_kernel(float* __restrict__ out, int C) {
    const float uniform = SMOOTHING / (float)(C - 1);
    const float conf    = 1.0f - SMOOTHING;
    const float cmu     = conf - uniform;

    float loss_sum = uniform * fmaf(g_sumw, g_lse_acc, -g_dot_acc)
                   + cmu * g_gold_acc;
    out[0] = loss_sum / (g_mask_acc + EPSILON);

    g_sumw = 0.0f; g_lse_acc = 0.0f; g_dot_acc = 0.0f;
    g_gold_acc = 0.0f; g_mask_acc = 0.0f;
}

extern "C" void kernel_launch(void* const* d_in, const int* in_sizes, int n_in,
                              void* d_out, int out_size)
{
    const float* logits = (const float*)d_in[0];
    const int*   gold   = (const int*)d_in[1];
    const int*   mask   = (const int*)d_in[2];
    const float* weight = (const float*)d_in[3];
    float*       out    = (float*)d_out;

    const int N = in_sizes[1];     // B*S rows
    const int C = in_sizes[3];     // classes
    const int C4 = C / 4;

    row_loss_kernel<<<N + SUMW_CTAS, 256>>>(logits, gold, mask, weight, C4, C, N);
    finalize3_kernel<<<1, 1>>>(out, C);
}